// round 16
// baseline (speedup 1.0000x reference)
#include <cuda_runtime.h>
#include <cuda_fp16.h>
#include <cstdint>
#include <cstddef>

#define NROWS 131072
#define PDIM 256
#define HID 1024
#define LN_EPS 1e-5f

// ---------------- scratch (device globals; allocation-free rule) ----------------
static __device__ __half d_H[(size_t)NROWS * HID];    // 256MB: (XW1+b1) fp16 -> LN/gelu in-place
static __device__ __half d_X[(size_t)NROWS * PDIM];   // 64MB: gathered player embeddings fp16
static __device__ __half d_W1h[PDIM * HID];           // W1p fp16 [K][N]
static __device__ __half d_W2h[HID * HID];            // W2p fp16 [K][N]

__device__ __forceinline__ uint32_t smem_u32(const void* p) {
    uint32_t a;
    asm("{ .reg .u64 t; cvta.to.shared.u64 t, %1; cvt.u32.u64 %0, t; }" : "=r"(a) : "l"(p));
    return a;
}
#define CP16(sm, gp)  asm volatile("cp.async.cg.shared.global [%0], [%1], 16;" :: "r"(sm), "l"(gp))
#define CP_COMMIT()   asm volatile("cp.async.commit_group;" ::: "memory")
#define CP_WAIT1()    asm volatile("cp.async.wait_group 1;" ::: "memory")

__device__ __forceinline__ void ldsm_x4(uint32_t* r, uint32_t addr) {
    asm volatile("ldmatrix.sync.aligned.m8n8.x4.shared.b16 {%0,%1,%2,%3}, [%4];"
                 : "=r"(r[0]), "=r"(r[1]), "=r"(r[2]), "=r"(r[3]) : "r"(addr));
}
__device__ __forceinline__ void ldsm_x4_t(uint32_t* r, uint32_t addr) {
    asm volatile("ldmatrix.sync.aligned.m8n8.x4.trans.shared.b16 {%0,%1,%2,%3}, [%4];"
                 : "=r"(r[0]), "=r"(r[1]), "=r"(r[2]), "=r"(r[3]) : "r"(addr));
}
__device__ __forceinline__ void mma16816(float* c, const uint32_t* a, const uint32_t* b) {
    asm volatile("mma.sync.aligned.m16n8k16.row.col.f32.f16.f16.f32 "
                 "{%0,%1,%2,%3}, {%4,%5,%6,%7}, {%8,%9}, {%0,%1,%2,%3};"
                 : "+f"(c[0]), "+f"(c[1]), "+f"(c[2]), "+f"(c[3])
                 : "r"(a[0]), "r"(a[1]), "r"(a[2]), "r"(a[3]), "r"(b[0]), "r"(b[1]));
}

// fast exact-enough gelu: Abramowitz-Stegun 7.1.26 erf (abs err <= 1.5e-7)
__device__ __forceinline__ float fast_gelu(float x) {
    float z = 0.70710678118654752f * x;
    float a = fabsf(z);
    float t = __fdividef(1.0f, fmaf(0.3275911f, a, 1.0f));
    float p = t * fmaf(t, fmaf(t, fmaf(t, fmaf(t, 1.061405429f, -1.453152027f),
                                       1.421413741f), -0.284496736f), 0.254829592f);
    float e = p * __expf(-z * z);
    float erfv = copysignf(1.0f - e, z);
    return fmaf(0.5f * x, erfv, 0.5f * x);
}

// ---------------- GEMM config: 128x128x32, 3 stages, 2 CTAs/SM ----------------
#define BM 128
#define BN 128
#define BK 32
#define STAGES 3
#define A_LDM 40                                  // halves; bank step 20 -> conflict-free
#define B_LDM 136                                 // halves; bank step 4  -> conflict-free
#define A_STAGE (BM * A_LDM * 2)
#define B_STAGE (BK * B_LDM * 2)
#define SM_A(s) ((s) * A_STAGE)
#define SM_B(s) (STAGES * A_STAGE + (s) * B_STAGE)
#define SMEM_GEMM (STAGES * (A_STAGE + B_STAGE))  // 56832 B

template <int K>
__device__ __forceinline__ void load_stage(uint32_t smb, int s, int kb,
                                           const __half* __restrict__ A,
                                           const __half* __restrict__ B,
                                           int rowBase, int colBase, int t) {
    const int k0 = kb * BK;
    const uint32_t sa = smb + SM_A(s);
#pragma unroll
    for (int q = 0; q < 2; q++) {                 // A: 128 rows x 32 halves
        int idx = q * 256 + t;
        int r = idx >> 2, c = idx & 3;
        CP16(sa + r * (A_LDM * 2) + c * 16, A + (size_t)(rowBase + r) * K + k0 + c * 8);
    }
    const uint32_t sb = smb + SM_B(s);
#pragma unroll
    for (int q = 0; q < 2; q++) {                 // B: 32 rows x 128 halves
        int idx = q * 256 + t;
        int r = idx >> 4, c = idx & 15;
        CP16(sb + r * (B_LDM * 2) + c * 16, B + (size_t)(k0 + r) * HID + colBase + c * 8);
    }
}

// C[128x128] = A[BM x K] @ B[K x HID slice] + bias;
// F32OUT ? fp32 out : fp16 -> outH (bias added in BOTH paths)
template <int K, bool F32OUT>
__global__ __launch_bounds__(256, 2) void mma_gemm_kernel(const __half* __restrict__ A,
                                                          const __half* __restrict__ B,
                                                          const float* __restrict__ bias,
                                                          float* __restrict__ outF,
                                                          __half* __restrict__ outH) {
    extern __shared__ __align__(1024) char sm[];
    const uint32_t smb = smem_u32(sm);
    const int t = threadIdx.x, lane = t & 31, warp = t >> 5;
    const int wm = warp >> 2, wn = warp & 3;      // 2 x 4 warps, 64x32 each
    const int rowBase = blockIdx.y * BM, colBase = blockIdx.x * BN;
    constexpr int KB = K / BK;

    float c[4][4][4];
#pragma unroll
    for (int mi = 0; mi < 4; mi++)
#pragma unroll
        for (int ni = 0; ni < 4; ni++)
#pragma unroll
            for (int e = 0; e < 4; e++) c[mi][ni][e] = 0.0f;

    const int a_row = lane & 15;
    const int a_kb  = (lane >> 4) * 16;           // bytes
    const int b_krow = ((lane >> 3) & 1) * 8 + (lane & 7);
    const int b_ncol = (lane >> 4) * 8;

#pragma unroll
    for (int s = 0; s < STAGES - 1; s++) {
        load_stage<K>(smb, s, s, A, B, rowBase, colBase, t);
        CP_COMMIT();
    }

    for (int kb = 0; kb < KB; kb++) {
        CP_WAIT1();
        __syncthreads();
        const int nxt = kb + STAGES - 1;
        if (nxt < KB) load_stage<K>(smb, nxt % STAGES, nxt, A, B, rowBase, colBase, t);
        CP_COMMIT();

        const uint32_t aoff = smb + SM_A(kb % STAGES);
        const uint32_t boff = smb + SM_B(kb % STAGES);
#pragma unroll
        for (int s16 = 0; s16 < 2; s16++) {
            uint32_t a[4][4];
#pragma unroll
            for (int mi = 0; mi < 4; mi++)
                ldsm_x4(a[mi], aoff + (wm * 64 + mi * 16 + a_row) * (A_LDM * 2)
                                    + s16 * 32 + a_kb);
            uint32_t b[4][2];
#pragma unroll
            for (int np = 0; np < 2; np++) {
                uint32_t r4[4];
                ldsm_x4_t(r4, boff + (s16 * 16 + b_krow) * (B_LDM * 2)
                                   + (wn * 32 + np * 16 + b_ncol) * 2);
                b[np * 2][0] = r4[0]; b[np * 2][1] = r4[1];
                b[np * 2 + 1][0] = r4[2]; b[np * 2 + 1][1] = r4[3];
            }
#pragma unroll
            for (int mi = 0; mi < 4; mi++)
#pragma unroll
                for (int ni = 0; ni < 4; ni++) mma16816(c[mi][ni], a[mi], b[ni]);
        }
    }

    // ---- epilogue: +bias, direct register -> global ----
    const int cr = lane >> 2, cc = (lane & 3) * 2;
    float bias2[4][2];
#pragma unroll
    for (int ni = 0; ni < 4; ni++) {
        int gcol = colBase + wn * 32 + ni * 8 + cc;
        bias2[ni][0] = __ldg(bias + gcol);
        bias2[ni][1] = __ldg(bias + gcol + 1);
    }
#pragma unroll
    for (int mi = 0; mi < 4; mi++) {
        const int grow = rowBase + wm * 64 + mi * 16 + cr;
#pragma unroll
        for (int ni = 0; ni < 4; ni++) {
            const int gcol = colBase + wn * 32 + ni * 8 + cc;
            float v0 = c[mi][ni][0] + bias2[ni][0];
            float v1 = c[mi][ni][1] + bias2[ni][1];
            float v2 = c[mi][ni][2] + bias2[ni][0];
            float v3 = c[mi][ni][3] + bias2[ni][1];
            if (F32OUT) {
                *(float2*)(outF + (size_t)grow * HID + gcol) = make_float2(v0, v1);
                *(float2*)(outF + (size_t)(grow + 8) * HID + gcol) = make_float2(v2, v3);
            } else {
                *(__half2*)(outH + (size_t)grow * HID + gcol) = __floats2half2_rn(v0, v1);
                *(__half2*)(outH + (size_t)(grow + 8) * HID + gcol) = __floats2half2_rn(v2, v3);
            }
        }
    }
}

// ---------------- merged prep: gather + convw ----------------
__global__ __launch_bounds__(256) void prep_kernel(const int* __restrict__ pid,
                                                   const float* __restrict__ ptab,
                                                   const float* __restrict__ w1,
                                                   const float* __restrict__ w2) {
    const size_t gid = (size_t)blockIdx.x * 256 + threadIdx.x;
    {
        const int row = (int)(gid >> 5), ch = (int)(gid & 31);
        const float* gp = ptab + (size_t)pid[row] * PDIM + ch * 8;
        float4 f0 = *(const float4*)gp;
        float4 f1 = *(const float4*)(gp + 4);
        __align__(16) __half2 h[4];
        h[0] = __floats2half2_rn(f0.x, f0.y);
        h[1] = __floats2half2_rn(f0.z, f0.w);
        h[2] = __floats2half2_rn(f1.x, f1.y);
        h[3] = __floats2half2_rn(f1.z, f1.w);
        *(uint4*)(d_X + (size_t)row * PDIM + ch * 8) = *(uint4*)h;
    }
    if (gid < HID * HID / 8) {
        const int i8 = (int)gid;
        if (i8 < PDIM * HID / 8) {
            const float* gp = w1 + (size_t)i8 * 8;
            float4 f0 = *(const float4*)gp, f1 = *(const float4*)(gp + 4);
            __align__(16) __half2 h[4];
            h[0] = __floats2half2_rn(f0.x, f0.y); h[1] = __floats2half2_rn(f0.z, f0.w);
            h[2] = __floats2half2_rn(f1.x, f1.y); h[3] = __floats2half2_rn(f1.z, f1.w);
            *(uint4*)(d_W1h + (size_t)i8 * 8) = *(uint4*)h;
        }
        const float* gp = w2 + (size_t)i8 * 8;
        float4 f0 = *(const float4*)gp, f1 = *(const float4*)(gp + 4);
        __align__(16) __half2 h[4];
        h[0] = __floats2half2_rn(f0.x, f0.y); h[1] = __floats2half2_rn(f0.z, f0.w);
        h[2] = __floats2half2_rn(f1.x, f1.y); h[3] = __floats2half2_rn(f1.z, f1.w);
        *(uint4*)(d_W2h + (size_t)i8 * 8) = *(uint4*)h;
    }
}

// ---------------- fused stats + LN + gelu, in-place on d_H (bias pre-folded) ----------------
__global__ __launch_bounds__(256) void ln_gelu_kernel(const float* __restrict__ g,
                                                      const float* __restrict__ beta) {
    __shared__ float sg[1024], se[1024];
    const int t = threadIdx.x;
#pragma unroll
    for (int i = 0; i < 4; i++) {
        int j = t + i * 256;
        sg[j] = g[j]; se[j] = beta[j];
    }
    __syncthreads();
    const int row = blockIdx.x * 8 + (t >> 5);
    const int lane = t & 31;
    __half* hrow = d_H + (size_t)row * HID;

    uint4 u[4];
    float v[32];
    float s = 0.f, ss = 0.f;
#pragma unroll
    for (int cc = 0; cc < 4; cc++) {
        u[cc] = *(uint4*)(hrow + cc * 256 + lane * 8);
        __half2* hp = (__half2*)&u[cc];
#pragma unroll
        for (int e = 0; e < 4; e++) {
            float2 f = __half22float2(hp[e]);
            v[cc * 8 + 2 * e] = f.x;
            v[cc * 8 + 2 * e + 1] = f.y;
            s += f.x + f.y;
            ss += f.x * f.x + f.y * f.y;
        }
    }
#pragma unroll
    for (int o = 16; o; o >>= 1) {
        s += __shfl_xor_sync(0xffffffffu, s, o);
        ss += __shfl_xor_sync(0xffffffffu, ss, o);
    }
    float mu = s * (1.0f / HID);
    float rs = rsqrtf(ss * (1.0f / HID) - mu * mu + LN_EPS);
#pragma unroll
    for (int cc = 0; cc < 4; cc++) {
        __half2* hp = (__half2*)&u[cc];
#pragma unroll
        for (int e = 0; e < 4; e++) {
            int col = cc * 256 + lane * 8 + 2 * e;
            float x0 = (v[cc * 8 + 2 * e] - mu) * rs * sg[col] + se[col];
            float x1 = (v[cc * 8 + 2 * e + 1] - mu) * rs * sg[col + 1] + se[col + 1];
            hp[e] = __floats2half2_rn(fast_gelu(x0), fast_gelu(x1));
        }
        *(uint4*)(hrow + cc * 256 + lane * 8) = u[cc];
    }
}

// ---------------- fallback with in-kernel strip scan (no global state) ----------------
#define FB_BLOCKS 64
#define FB_STRIP (NROWS / FB_BLOCKS)   // 2048 rows per block
#define FB_MAXLIST 64

__global__ __launch_bounds__(256) void fallback_kernel(
    const int* __restrict__ pid,
    const int* __restrict__ tid_, const int* __restrict__ rid,
    const float* __restrict__ team_tab, const float* __restrict__ role_tab,
    const float* __restrict__ W1f, const float* __restrict__ b1f,
    const float* __restrict__ gf, const float* __restrict__ bf,
    const float* __restrict__ W2f, const float* __restrict__ b2f,
    float* __restrict__ out) {
    __shared__ int list[FB_MAXLIST];
    __shared__ int cnt;
    __shared__ float in[192];
    __shared__ float hs[1024];
    __shared__ float red[32];
    const int t = threadIdx.x;
    const int base = blockIdx.x * FB_STRIP;

    if (t == 0) cnt = 0;
    __syncthreads();
    for (int i = t; i < FB_STRIP; i += 256) {
        if (pid[base + i] == 0) {
            int slot = atomicAdd(&cnt, 1);
            if (slot < FB_MAXLIST) list[slot] = base + i;
        }
    }
    __syncthreads();
    const int n = (cnt < FB_MAXLIST) ? cnt : FB_MAXLIST;

    for (int li = 0; li < n; li++) {
        const int row = list[li];
        int tt = tid_[row], rr = rid[row];
        __syncthreads();
        if (t < 128) in[t] = team_tab[tt * 128 + t];
        else if (t < 192) in[t] = role_tab[rr * 64 + (t - 128)];
        __syncthreads();
        float hv[4], s = 0.f, ss = 0.f;
#pragma unroll
        for (int q = 0; q < 4; q++) {
            int j = t + q * 256;
            float acc = b1f[j];
#pragma unroll 8
            for (int k = 0; k < 192; k++) acc += in[k] * W1f[k * 1024 + j];
            hv[q] = acc; s += acc; ss += acc * acc;
        }
#pragma unroll
        for (int o = 16; o; o >>= 1) {
            s += __shfl_xor_sync(0xffffffffu, s, o);
            ss += __shfl_xor_sync(0xffffffffu, ss, o);
        }
        if ((t & 31) == 0) { red[t >> 5] = s; red[8 + (t >> 5)] = ss; }
        __syncthreads();
        if (t == 0) {
            float S = 0.f, SS = 0.f;
            for (int w = 0; w < 8; w++) { S += red[w]; SS += red[8 + w]; }
            float mu = S / 1024.0f;
            red[16] = mu;
            red[17] = rsqrtf(SS / 1024.0f - mu * mu + LN_EPS);
        }
        __syncthreads();
        float mu = red[16], rs = red[17];
#pragma unroll
        for (int q = 0; q < 4; q++) {
            int j = t + q * 256;
            float v = (hv[q] - mu) * rs * gf[j] + bf[j];
            hs[j] = 0.5f * v * (1.0f + erff(v * 0.70710678118654752f));
        }
        __syncthreads();
#pragma unroll
        for (int q = 0; q < 4; q++) {
            int j = t + q * 256;
            float acc = b2f[j];
            for (int k = 0; k < 1024; k++) acc += hs[k] * W2f[k * 1024 + j];
            out[(size_t)row * 1024 + j] = acc;
        }
    }
}

// ---------------- launch ----------------
extern "C" void kernel_launch(void* const* d_in, const int* in_sizes, int n_in,
                              void* d_out, int out_size) {
    const int* pid = (const int*)d_in[0];
    const int* tid = (const int*)d_in[1];
    const int* rid = (const int*)d_in[2];
    const float* ptab = (const float*)d_in[3];
    const float* ttab = (const float*)d_in[4];
    const float* rtab = (const float*)d_in[5];
    const float* W1p = (const float*)d_in[6];
    const float* b1p = (const float*)d_in[7];
    const float* gp  = (const float*)d_in[8];
    const float* bp  = (const float*)d_in[9];
    const float* W2p = (const float*)d_in[10];
    const float* b2p = (const float*)d_in[11];
    const float* W1f = (const float*)d_in[12];
    const float* b1f = (const float*)d_in[13];
    const float* gf  = (const float*)d_in[14];
    const float* bf  = (const float*)d_in[15];
    const float* W2f = (const float*)d_in[16];
    const float* b2f = (const float*)d_in[17];
    float* out = (float*)d_out;

    cudaFuncSetAttribute(mma_gemm_kernel<PDIM, false>,
                         cudaFuncAttributeMaxDynamicSharedMemorySize, SMEM_GEMM);
    cudaFuncSetAttribute(mma_gemm_kernel<HID, true>,
                         cudaFuncAttributeMaxDynamicSharedMemorySize, SMEM_GEMM);

    __half *x, *h, *w1h, *w2h;
    cudaGetSymbolAddress((void**)&x, d_X);
    cudaGetSymbolAddress((void**)&h, d_H);
    cudaGetSymbolAddress((void**)&w1h, d_W1h);
    cudaGetSymbolAddress((void**)&w2h, d_W2h);

    prep_kernel<<<NROWS * 32 / 256, 256>>>(pid, ptab, W1p, W2p);
    mma_gemm_kernel<PDIM, false><<<dim3(HID / BN, NROWS / BM), 256, SMEM_GEMM>>>(
        x, w1h, b1p, nullptr, h);
    ln_gelu_kernel<<<NROWS / 8, 256>>>(gp, bp);
    mma_gemm_kernel<HID, true><<<dim3(HID / BN, NROWS / BM), 256, SMEM_GEMM>>>(
        h, w2h, b2p, out, nullptr);
    fallback_kernel<<<FB_BLOCKS, 256>>>(pid, tid, rid, ttab, rtab,
                                        W1f, b1f, gf, bf, W2f, b2f, out);
}

// round 17
// speedup vs baseline: 1.1099x; 1.1099x over previous
#include <cuda_runtime.h>
#include <cuda_fp16.h>
#include <cstdint>
#include <cstddef>

#define NROWS 131072
#define PDIM 256
#define HID 1024
#define LN_EPS 1e-5f

// ---------------- scratch (device globals; allocation-free rule) ----------------
static __device__ __half d_H[(size_t)NROWS * HID];    // 256MB: (XW1+b1) fp16 -> LN/gelu in-place
static __device__ __half d_X[(size_t)NROWS * PDIM];   // 64MB: gathered player embeddings fp16
static __device__ __half d_W1h[PDIM * HID];           // W1p fp16 [K][N]
static __device__ __half d_W2h[HID * HID];            // W2p fp16 [K][N]
static __device__ int d_unk[NROWS];
static __device__ int d_cnt;

__device__ __forceinline__ uint32_t smem_u32(const void* p) {
    uint32_t a;
    asm("{ .reg .u64 t; cvta.to.shared.u64 t, %1; cvt.u32.u64 %0, t; }" : "=r"(a) : "l"(p));
    return a;
}
#define CP16(sm, gp)  asm volatile("cp.async.cg.shared.global [%0], [%1], 16;" :: "r"(sm), "l"(gp))
#define CP_COMMIT()   asm volatile("cp.async.commit_group;" ::: "memory")
#define CP_WAIT1()    asm volatile("cp.async.wait_group 1;" ::: "memory")

__device__ __forceinline__ void ldsm_x4(uint32_t* r, uint32_t addr) {
    asm volatile("ldmatrix.sync.aligned.m8n8.x4.shared.b16 {%0,%1,%2,%3}, [%4];"
                 : "=r"(r[0]), "=r"(r[1]), "=r"(r[2]), "=r"(r[3]) : "r"(addr));
}
__device__ __forceinline__ void ldsm_x4_t(uint32_t* r, uint32_t addr) {
    asm volatile("ldmatrix.sync.aligned.m8n8.x4.trans.shared.b16 {%0,%1,%2,%3}, [%4];"
                 : "=r"(r[0]), "=r"(r[1]), "=r"(r[2]), "=r"(r[3]) : "r"(addr));
}
__device__ __forceinline__ void mma16816(float* c, const uint32_t* a, const uint32_t* b) {
    asm volatile("mma.sync.aligned.m16n8k16.row.col.f32.f16.f16.f32 "
                 "{%0,%1,%2,%3}, {%4,%5,%6,%7}, {%8,%9}, {%0,%1,%2,%3};"
                 : "+f"(c[0]), "+f"(c[1]), "+f"(c[2]), "+f"(c[3])
                 : "r"(a[0]), "r"(a[1]), "r"(a[2]), "r"(a[3]), "r"(b[0]), "r"(b[1]));
}

// fast exact-enough gelu: Abramowitz-Stegun 7.1.26 erf (abs err <= 1.5e-7)
__device__ __forceinline__ float fast_gelu(float x) {
    float z = 0.70710678118654752f * x;
    float a = fabsf(z);
    float t = __fdividef(1.0f, fmaf(0.3275911f, a, 1.0f));
    float p = t * fmaf(t, fmaf(t, fmaf(t, fmaf(t, 1.061405429f, -1.453152027f),
                                       1.421413741f), -0.284496736f), 0.254829592f);
    float e = p * __expf(-z * z);
    float erfv = copysignf(1.0f - e, z);
    return fmaf(0.5f * x, erfv, 0.5f * x);
}

// ---------------- GEMM config: 128x128x64, 3 stages, 2 CTAs/SM ----------------
#define BM 128
#define BN 128
#define BK 64
#define STAGES 3
#define A_LDM 72                                  // halves; bank step 4r -> conflict-free
#define B_LDM 136                                 // halves; bank step 4r -> conflict-free
#define A_STAGE (BM * A_LDM * 2)                  // 18432 B
#define B_STAGE (BK * B_LDM * 2)                  // 17408 B
#define SM_A(s) ((s) * A_STAGE)
#define SM_B(s) (STAGES * A_STAGE + (s) * B_STAGE)
#define SMEM_GEMM (STAGES * (A_STAGE + B_STAGE))  // 107520 B; 2 CTAs = 215KB <= 228KB

template <int K>
__device__ __forceinline__ void load_stage(uint32_t smb, int s, int kb,
                                           const __half* __restrict__ A,
                                           const __half* __restrict__ B,
                                           int rowBase, int colBase, int t) {
    const int k0 = kb * BK;
    const uint32_t sa = smb + SM_A(s);
#pragma unroll
    for (int q = 0; q < 4; q++) {                 // A: 128 rows x 64 halves (8x16B/row)
        int idx = q * 256 + t;
        int r = idx >> 3, c = idx & 7;
        CP16(sa + r * (A_LDM * 2) + c * 16, A + (size_t)(rowBase + r) * K + k0 + c * 8);
    }
    const uint32_t sb = smb + SM_B(s);
#pragma unroll
    for (int q = 0; q < 4; q++) {                 // B: 64 rows x 128 halves (16x16B/row)
        int idx = q * 256 + t;
        int r = idx >> 4, c = idx & 15;
        CP16(sb + r * (B_LDM * 2) + c * 16, B + (size_t)(k0 + r) * HID + colBase + c * 8);
    }
}

// C[128x128] = A[BM x K] @ B[K x HID slice] + bias;
// F32OUT ? fp32 out : fp16 -> outH (bias added in BOTH paths)
template <int K, bool F32OUT>
__global__ __launch_bounds__(256, 2) void mma_gemm_kernel(const __half* __restrict__ A,
                                                          const __half* __restrict__ B,
                                                          const float* __restrict__ bias,
                                                          float* __restrict__ outF,
                                                          __half* __restrict__ outH) {
    extern __shared__ __align__(1024) char sm[];
    const uint32_t smb = smem_u32(sm);
    const int t = threadIdx.x, lane = t & 31, warp = t >> 5;
    const int wm = warp >> 2, wn = warp & 3;      // 2 x 4 warps, 64x32 each
    const int rowBase = blockIdx.y * BM, colBase = blockIdx.x * BN;
    constexpr int KB = K / BK;

    float c[4][4][4];
#pragma unroll
    for (int mi = 0; mi < 4; mi++)
#pragma unroll
        for (int ni = 0; ni < 4; ni++)
#pragma unroll
            for (int e = 0; e < 4; e++) c[mi][ni][e] = 0.0f;

    const int a_row = lane & 15;
    const int a_kb  = (lane >> 4) * 16;           // bytes
    const int b_krow = ((lane >> 3) & 1) * 8 + (lane & 7);
    const int b_ncol = (lane >> 4) * 8;

#pragma unroll
    for (int s = 0; s < STAGES - 1; s++) {
        load_stage<K>(smb, s, s, A, B, rowBase, colBase, t);
        CP_COMMIT();
    }

    for (int kb = 0; kb < KB; kb++) {
        CP_WAIT1();
        __syncthreads();
        const int nxt = kb + STAGES - 1;
        if (nxt < KB) load_stage<K>(smb, nxt % STAGES, nxt, A, B, rowBase, colBase, t);
        CP_COMMIT();

        const uint32_t aoff = smb + SM_A(kb % STAGES);
        const uint32_t boff = smb + SM_B(kb % STAGES);
#pragma unroll
        for (int s16 = 0; s16 < 4; s16++) {       // 4 k16 chunks per BK=64
            uint32_t a[4][4];
#pragma unroll
            for (int mi = 0; mi < 4; mi++)
                ldsm_x4(a[mi], aoff + (wm * 64 + mi * 16 + a_row) * (A_LDM * 2)
                                    + s16 * 32 + a_kb);
            uint32_t b[4][2];
#pragma unroll
            for (int np = 0; np < 2; np++) {
                uint32_t r4[4];
                ldsm_x4_t(r4, boff + (s16 * 16 + b_krow) * (B_LDM * 2)
                                   + (wn * 32 + np * 16 + b_ncol) * 2);
                b[np * 2][0] = r4[0]; b[np * 2][1] = r4[1];
                b[np * 2 + 1][0] = r4[2]; b[np * 2 + 1][1] = r4[3];
            }
#pragma unroll
            for (int mi = 0; mi < 4; mi++)
#pragma unroll
                for (int ni = 0; ni < 4; ni++) mma16816(c[mi][ni], a[mi], b[ni]);
        }
    }

    // ---- epilogue: +bias, direct register -> global ----
    const int cr = lane >> 2, cc = (lane & 3) * 2;
    float bias2[4][2];
#pragma unroll
    for (int ni = 0; ni < 4; ni++) {
        int gcol = colBase + wn * 32 + ni * 8 + cc;
        bias2[ni][0] = __ldg(bias + gcol);
        bias2[ni][1] = __ldg(bias + gcol + 1);
    }
#pragma unroll
    for (int mi = 0; mi < 4; mi++) {
        const int grow = rowBase + wm * 64 + mi * 16 + cr;
#pragma unroll
        for (int ni = 0; ni < 4; ni++) {
            const int gcol = colBase + wn * 32 + ni * 8 + cc;
            float v0 = c[mi][ni][0] + bias2[ni][0];
            float v1 = c[mi][ni][1] + bias2[ni][1];
            float v2 = c[mi][ni][2] + bias2[ni][0];
            float v3 = c[mi][ni][3] + bias2[ni][1];
            if (F32OUT) {
                *(float2*)(outF + (size_t)grow * HID + gcol) = make_float2(v0, v1);
                *(float2*)(outF + (size_t)(grow + 8) * HID + gcol) = make_float2(v2, v3);
            } else {
                *(__half2*)(outH + (size_t)grow * HID + gcol) = __floats2half2_rn(v0, v1);
                *(__half2*)(outH + (size_t)(grow + 8) * HID + gcol) = __floats2half2_rn(v2, v3);
            }
        }
    }
}

// ---------------- merged prep: gather + convw + scan ----------------
__global__ __launch_bounds__(256) void prep_kernel(const int* __restrict__ pid,
                                                   const float* __restrict__ ptab,
                                                   const float* __restrict__ w1,
                                                   const float* __restrict__ w2) {
    const size_t gid = (size_t)blockIdx.x * 256 + threadIdx.x;
    {
        const int row = (int)(gid >> 5), ch = (int)(gid & 31);
        const float* gp = ptab + (size_t)pid[row] * PDIM + ch * 8;
        float4 f0 = *(const float4*)gp;
        float4 f1 = *(const float4*)(gp + 4);
        __align__(16) __half2 h[4];
        h[0] = __floats2half2_rn(f0.x, f0.y);
        h[1] = __floats2half2_rn(f0.z, f0.w);
        h[2] = __floats2half2_rn(f1.x, f1.y);
        h[3] = __floats2half2_rn(f1.z, f1.w);
        *(uint4*)(d_X + (size_t)row * PDIM + ch * 8) = *(uint4*)h;
    }
    if (gid < HID * HID / 8) {
        const int i8 = (int)gid;
        if (i8 < PDIM * HID / 8) {
            const float* gp = w1 + (size_t)i8 * 8;
            float4 f0 = *(const float4*)gp, f1 = *(const float4*)(gp + 4);
            __align__(16) __half2 h[4];
            h[0] = __floats2half2_rn(f0.x, f0.y); h[1] = __floats2half2_rn(f0.z, f0.w);
            h[2] = __floats2half2_rn(f1.x, f1.y); h[3] = __floats2half2_rn(f1.z, f1.w);
            *(uint4*)(d_W1h + (size_t)i8 * 8) = *(uint4*)h;
        }
        const float* gp = w2 + (size_t)i8 * 8;
        float4 f0 = *(const float4*)gp, f1 = *(const float4*)(gp + 4);
        __align__(16) __half2 h[4];
        h[0] = __floats2half2_rn(f0.x, f0.y); h[1] = __floats2half2_rn(f0.z, f0.w);
        h[2] = __floats2half2_rn(f1.x, f1.y); h[3] = __floats2half2_rn(f1.z, f1.w);
        *(uint4*)(d_W2h + (size_t)i8 * 8) = *(uint4*)h;
    }
    if (gid < NROWS && pid[gid] == 0) {
        int slot = atomicAdd(&d_cnt, 1);
        d_unk[slot] = (int)gid;
    }
}

// ---------------- fused stats + LN + gelu, in-place on d_H (bias pre-folded) ----------------
__global__ __launch_bounds__(256) void ln_gelu_kernel(const float* __restrict__ g,
                                                      const float* __restrict__ beta) {
    __shared__ float sg[1024], se[1024];
    const int t = threadIdx.x;
#pragma unroll
    for (int i = 0; i < 4; i++) {
        int j = t + i * 256;
        sg[j] = g[j]; se[j] = beta[j];
    }
    __syncthreads();
    const int row = blockIdx.x * 8 + (t >> 5);
    const int lane = t & 31;
    __half* hrow = d_H + (size_t)row * HID;

    uint4 u[4];
    float v[32];
    float s = 0.f, ss = 0.f;
#pragma unroll
    for (int cc = 0; cc < 4; cc++) {
        u[cc] = *(uint4*)(hrow + cc * 256 + lane * 8);
        __half2* hp = (__half2*)&u[cc];
#pragma unroll
        for (int e = 0; e < 4; e++) {
            float2 f = __half22float2(hp[e]);
            v[cc * 8 + 2 * e] = f.x;
            v[cc * 8 + 2 * e + 1] = f.y;
            s += f.x + f.y;
            ss += f.x * f.x + f.y * f.y;
        }
    }
#pragma unroll
    for (int o = 16; o; o >>= 1) {
        s += __shfl_xor_sync(0xffffffffu, s, o);
        ss += __shfl_xor_sync(0xffffffffu, ss, o);
    }
    float mu = s * (1.0f / HID);
    float rs = rsqrtf(ss * (1.0f / HID) - mu * mu + LN_EPS);
#pragma unroll
    for (int cc = 0; cc < 4; cc++) {
        __half2* hp = (__half2*)&u[cc];
#pragma unroll
        for (int e = 0; e < 4; e++) {
            int col = cc * 256 + lane * 8 + 2 * e;
            float x0 = (v[cc * 8 + 2 * e] - mu) * rs * sg[col] + se[col];
            float x1 = (v[cc * 8 + 2 * e + 1] - mu) * rs * sg[col + 1] + se[col + 1];
            hp[e] = __floats2half2_rn(fast_gelu(x0), fast_gelu(x1));
        }
        *(uint4*)(hrow + cc * 256 + lane * 8) = u[cc];
    }
}

// ---------------- fallback (R15 structure) ----------------
__global__ void zero_cnt_kernel() { if (threadIdx.x == 0) d_cnt = 0; }

__global__ __launch_bounds__(256) void fallback_kernel(
    const int* __restrict__ tid_, const int* __restrict__ rid,
    const float* __restrict__ team_tab, const float* __restrict__ role_tab,
    const float* __restrict__ W1f, const float* __restrict__ b1f,
    const float* __restrict__ gf, const float* __restrict__ bf,
    const float* __restrict__ W2f, const float* __restrict__ b2f,
    float* __restrict__ out) {
    __shared__ float in[192];
    __shared__ float hs[1024];
    __shared__ float red[32];
    const int t = threadIdx.x;
    const int n = d_cnt;
    for (int li = blockIdx.x; li < n; li += gridDim.x) {
        const int row = d_unk[li];
        int tt = tid_[row], rr = rid[row];
        __syncthreads();
        if (t < 128) in[t] = team_tab[tt * 128 + t];
        else if (t < 192) in[t] = role_tab[rr * 64 + (t - 128)];
        __syncthreads();
        float hv[4], s = 0.f, ss = 0.f;
#pragma unroll
        for (int q = 0; q < 4; q++) {
            int j = t + q * 256;
            float acc = b1f[j];
#pragma unroll 8
            for (int k = 0; k < 192; k++) acc += in[k] * W1f[k * 1024 + j];
            hv[q] = acc; s += acc; ss += acc * acc;
        }
#pragma unroll
        for (int o = 16; o; o >>= 1) {
            s += __shfl_xor_sync(0xffffffffu, s, o);
            ss += __shfl_xor_sync(0xffffffffu, ss, o);
        }
        if ((t & 31) == 0) { red[t >> 5] = s; red[8 + (t >> 5)] = ss; }
        __syncthreads();
        if (t == 0) {
            float S = 0.f, SS = 0.f;
            for (int w = 0; w < 8; w++) { S += red[w]; SS += red[8 + w]; }
            float mu = S / 1024.0f;
            red[16] = mu;
            red[17] = rsqrtf(SS / 1024.0f - mu * mu + LN_EPS);
        }
        __syncthreads();
        float mu = red[16], rs = red[17];
#pragma unroll
        for (int q = 0; q < 4; q++) {
            int j = t + q * 256;
            float v = (hv[q] - mu) * rs * gf[j] + bf[j];
            hs[j] = 0.5f * v * (1.0f + erff(v * 0.70710678118654752f));
        }
        __syncthreads();
#pragma unroll
        for (int q = 0; q < 4; q++) {
            int j = t + q * 256;
            float acc = b2f[j];
            for (int k = 0; k < 1024; k++) acc += hs[k] * W2f[k * 1024 + j];
            out[(size_t)row * 1024 + j] = acc;
        }
    }
}

// ---------------- launch ----------------
extern "C" void kernel_launch(void* const* d_in, const int* in_sizes, int n_in,
                              void* d_out, int out_size) {
    const int* pid = (const int*)d_in[0];
    const int* tid = (const int*)d_in[1];
    const int* rid = (const int*)d_in[2];
    const float* ptab = (const float*)d_in[3];
    const float* ttab = (const float*)d_in[4];
    const float* rtab = (const float*)d_in[5];
    const float* W1p = (const float*)d_in[6];
    const float* b1p = (const float*)d_in[7];
    const float* gp  = (const float*)d_in[8];
    const float* bp  = (const float*)d_in[9];
    const float* W2p = (const float*)d_in[10];
    const float* b2p = (const float*)d_in[11];
    const float* W1f = (const float*)d_in[12];
    const float* b1f = (const float*)d_in[13];
    const float* gf  = (const float*)d_in[14];
    const float* bf  = (const float*)d_in[15];
    const float* W2f = (const float*)d_in[16];
    const float* b2f = (const float*)d_in[17];
    float* out = (float*)d_out;

    cudaFuncSetAttribute(mma_gemm_kernel<PDIM, false>,
                         cudaFuncAttributeMaxDynamicSharedMemorySize, SMEM_GEMM);
    cudaFuncSetAttribute(mma_gemm_kernel<HID, true>,
                         cudaFuncAttributeMaxDynamicSharedMemorySize, SMEM_GEMM);

    __half *x, *h, *w1h, *w2h;
    cudaGetSymbolAddress((void**)&x, d_X);
    cudaGetSymbolAddress((void**)&h, d_H);
    cudaGetSymbolAddress((void**)&w1h, d_W1h);
    cudaGetSymbolAddress((void**)&w2h, d_W2h);

    zero_cnt_kernel<<<1, 32>>>();
    prep_kernel<<<NROWS * 32 / 256, 256>>>(pid, ptab, W1p, W2p);
    mma_gemm_kernel<PDIM, false><<<dim3(HID / BN, NROWS / BM), 256, SMEM_GEMM>>>(
        x, w1h, b1p, nullptr, h);
    ln_gelu_kernel<<<NROWS / 8, 256>>>(gp, bp);
    mma_gemm_kernel<HID, true><<<dim3(HID / BN, NROWS / BM), 256, SMEM_GEMM>>>(
        h, w2h, b2p, out, nullptr);
    fallback_kernel<<<64, 256>>>(tid, rid, ttab, rtab,
                                 W1f, b1f, gf, bf, W2f, b2f, out);
}